// round 16
// baseline (speedup 1.0000x reference)
#include <cuda_runtime.h>
#include <cuda_fp16.h>
#include <cstdint>

// ---------------- scratch (no mallocs allowed) ----------------
__device__ float g_S[8 * 4 * 18 * 4096];        // conv tap partials, 9.4 MB
__device__ float g_offset[4 * 2 * 4096];        // [b][oc][pix]
// B fp16 mma-fragment order: [b][nt:32][kg:64][n8:16][lane:32][4]  (33.5 MB)
__device__ __half g_Bfrag[4ULL * 32 * 64 * 2048];
// A fp16 mma-fragment order: [mt:16][kg:64][m16:8][lane:32][8]     (4 MB)
__device__ __half g_Afrag[16ULL * 64 * 2048];

#define FMA2(d, a, b, c) \
    asm("fma.rn.f32x2 %0, %1, %2, %3;" : "=l"(d) : "l"(a), "l"(b), "l"(c))

// =====================================================================
// Kernel 1: fused (a) offset-conv tap reduction [z 0..7, 256 ch/split]
// and (b) w_def -> fp16 A-fragment repack [z 8..23, 1 unit/block].
// Conv: 8 splits only -> g_S round-trip drops 75 MB -> 19 MB.
// Thread-halves split the 18 taps (9 each); 2 pixel-pairs per thread.
// =====================================================================
__global__ __launch_bounds__(256, 2) void conv_wdef_kernel(
    const float* __restrict__ refer, const float* __restrict__ sup,
    const float* __restrict__ w_off, const float* __restrict__ wd)
{
    if (blockIdx.z >= 8) {
        // ---- w_def repack: 512 blocks, 1 unit (256 items) each ----
        int bid = (blockIdx.z - 8) * 32 + blockIdx.y * 8 + blockIdx.x;  // 0..511
        int t = bid * 256 + threadIdx.x;              // (o, kg)
        int o = t >> 6, kg = t & 63;
        int mt = o >> 7, mrow = o & 127;
        int m16 = mrow >> 4, r16 = mrow & 15;
        int g = r16 & 7, hi = r16 >> 3;

        const float* src = wd + (size_t)o * 1024 + kg * 16;
        __half2* dst2 =
            (__half2*)(g_Afrag + (((size_t)mt * 64 + kg) * 8 + m16) * 256);

        #pragma unroll
        for (int p = 0; p < 8; ++p) {
            int c = p * 2;
            int tg = (c & 7) >> 1, chi = c >> 3;
            int lane = g * 4 + tg, reg = hi + 2 * chi;
            dst2[lane * 4 + reg] = __floats2half2_rn(src[c], src[c + 1]);
        }
        return;
    }

    // ---- conv tap reduction: 256 channels per split, taps split 9/9 ----
    __shared__ float2 wsh[256 * 18];                  // 36 KB

    int split = blockIdx.z;
    int b     = blockIdx.y;
    int c0    = split * 256;
    int tid   = threadIdx.x;
    int half  = tid >> 7;               // 0: taps 0-8 (oc0), 1: taps 9-17 (oc1)
    int lt    = tid & 127;

    for (int i = tid; i < 256 * 18; i += 256) {
        int c = i / 18, tap = i - c * 18;
        int oc = tap / 9, t9 = tap - oc * 9;
        float w = w_off[((size_t)oc * 2048 + c0 + c) * 9 + t9];
        wsh[i] = make_float2(w, w);
    }
    __syncthreads();

    const float* src = (c0 < 1024)
        ? refer + ((size_t)b * 1024 + c0) * 4096
        : sup   + ((size_t)b * 1024 + (c0 - 1024)) * 4096;

    // block covers 512 pixels: pair p at px = bx*512 + p*256 + lt*2
    int pxb = blockIdx.x * 512 + lt * 2;
    int toff = half * 9;

    unsigned long long acc[9][2];
    #pragma unroll
    for (int t = 0; t < 9; ++t) {
        acc[t][0] = 0ull;
        acc[t][1] = 0ull;
    }

    #pragma unroll 2
    for (int c = 0; c < 256; ++c) {
        const float* chan = src + (size_t)c * 4096 + pxb;
        unsigned long long v0 = *(const unsigned long long*)(chan);
        unsigned long long v1 = *(const unsigned long long*)(chan + 256);

        const unsigned long long* wp =
            (const unsigned long long*)&wsh[c * 18 + toff];
        #pragma unroll
        for (int t = 0; t < 9; ++t) {
            unsigned long long wv = wp[t];
            FMA2(acc[t][0], wv, v0, acc[t][0]);
            FMA2(acc[t][1], wv, v1, acc[t][1]);
        }
    }

    float* outb = g_S + (((size_t)split * 4 + b) * 18) * 4096 + pxb;
    #pragma unroll
    for (int t = 0; t < 9; ++t) {
        float* orow = outb + (size_t)(toff + t) * 4096;
        *(unsigned long long*)(orow)       = acc[t][0];
        *(unsigned long long*)(orow + 256) = acc[t][1];
    }
}

// =====================================================================
// Kernel 2: combine shifted taps + reduce 8 splits -> offsets.
// 4 threads per pixel (each 2 splits), batched loads, shfl reduce.
// Grid (64,4).
// =====================================================================
__global__ void offset_combine_kernel(const float* __restrict__ b_off)
{
    int b  = blockIdx.y;
    int pl = threadIdx.x >> 2;          // 0..63 pixel within block
    int q  = threadIdx.x & 3;           // splits q*2 .. q*2+1
    int pix = blockIdx.x * 64 + pl;
    int y = pix >> 6, x = pix & 63;

    float a0[2] = {0.f, 0.f};
    float a1[2] = {0.f, 0.f};
    int s0 = q * 2;

    #pragma unroll
    for (int ky = 0; ky < 3; ++ky) {
        int yy = y + ky - 1;
        bool vy = (yy >= 0) && (yy < 64);
        #pragma unroll
        for (int kx = 0; kx < 3; ++kx) {
            int xx = x + kx - 1;
            if (vy && xx >= 0 && xx < 64) {
                int sp = yy * 64 + xx;
                int t9 = ky * 3 + kx;
                #pragma unroll
                for (int ds = 0; ds < 2; ++ds) {
                    const float* Sb =
                        g_S + (((size_t)(s0 + ds) * 4 + b) * 18) * 4096 + sp;
                    a0[ds] += Sb[(size_t)t9 * 4096];
                    a1[ds] += Sb[(size_t)(9 + t9) * 4096];
                }
            }
        }
    }

    float r0 = a0[0] + a0[1];
    float r1 = a1[0] + a1[1];

    r0 += __shfl_xor_sync(0xFFFFFFFF, r0, 1);
    r0 += __shfl_xor_sync(0xFFFFFFFF, r0, 2);
    r1 += __shfl_xor_sync(0xFFFFFFFF, r1, 1);
    r1 += __shfl_xor_sync(0xFFFFFFFF, r1, 2);

    if (q == 0) {
        g_offset[(b * 2 + 0) * 4096 + pix] = r0 + b_off[0];
        g_offset[(b * 2 + 1) * 4096 + pix] = r1 + b_off[1];
    }
}

// =====================================================================
// Kernel 3: bilinear gather-sample -> B in fp16 mma-fragment order.
// Grid (16 pix strips, 4 batch, 16 channel-64 groups) = 1024 CTAs.
// =====================================================================
__global__ __launch_bounds__(256) void sample_kernel(
    const float* __restrict__ sup)
{
    int pix = blockIdx.x * 256 + threadIdx.x;
    int b   = blockIdx.y;
    int cq  = blockIdx.z;          // 0..15, 64 channels each

    float o0 = g_offset[(b * 2 + 0) * 4096 + pix];
    float o1 = g_offset[(b * 2 + 1) * 4096 + pix];

    int h = pix >> 6, w = pix & 63;
    float py = o0 + (float)h;
    float px = o1 + (float)w;
    float y0f = floorf(py), x0f = floorf(px);
    float wy = py - y0f, wx = px - x0f;
    int y0 = (int)y0f, x0 = (int)x0f;
    int y1 = y0 + 1,  x1 = x0 + 1;

    float vy0 = (y0 >= 0 && y0 < 64) ? 1.f : 0.f;
    float vy1 = (y1 >= 0 && y1 < 64) ? 1.f : 0.f;
    float vx0 = (x0 >= 0 && x0 < 64) ? 1.f : 0.f;
    float vx1 = (x1 >= 0 && x1 < 64) ? 1.f : 0.f;
    int cy0 = min(max(y0, 0), 63), cy1 = min(max(y1, 0), 63);
    int cx0 = min(max(x0, 0), 63), cx1 = min(max(x1, 0), 63);
    int i00 = cy0 * 64 + cx0, i01 = cy0 * 64 + cx1;
    int i10 = cy1 * 64 + cx0, i11 = cy1 * 64 + cx1;
    float w00 = (1.f - wy) * (1.f - wx) * vy0 * vx0;
    float w01 = (1.f - wy) * wx         * vy0 * vx1;
    float w10 = wy * (1.f - wx)         * vy1 * vx0;
    float w11 = wy * wx                 * vy1 * vx1;

    const float* base = sup + ((size_t)b * 1024 + cq * 64) * 4096;

    int nt = pix >> 7, n8 = (pix >> 3) & 15, g = pix & 7;
    __half* outb = g_Bfrag + (((size_t)b * 32 + nt) * 64) * 2048;

    union { uint4 u[2]; __half hbuf[16]; } pack;

    #pragma unroll
    for (int kg16 = 0; kg16 < 4; ++kg16) {
        int kg = cq * 4 + kg16;
        #pragma unroll
        for (int c = 0; c < 16; ++c) {
            const float* p = base + (size_t)(kg16 * 16 + c) * 4096;
            float r = w00 * p[i00] + w01 * p[i01] + w10 * p[i10] + w11 * p[i11];
            int idx = ((c & 7) >> 1) * 4 + (c >> 3) * 2 + (c & 1);
            pack.hbuf[idx] = __float2half_rn(r);
        }
        __half* dst = outb + ((size_t)kg * 16 + n8) * 128 + g * 16;
        *(uint4*)dst       = pack.u[0];
        *(uint4*)(dst + 8) = pack.u[1];
    }
}

// =====================================================================
// Kernel 4: fp16 mma.sync GEMM (m16n8k16, f32 accum).  [frozen]
// 128-thread CTAs: 4 warps (2x2) of 64x64 warp tiles -> CTA 128x128.
// k-tile 64, 3-stage cp.async (96 KB), 2 CTAs/SM.
// =====================================================================
__device__ __forceinline__ void mma_f16(float* c, const uint32_t* a, const uint32_t* bb) {
    asm volatile(
        "mma.sync.aligned.m16n8k16.row.col.f32.f16.f16.f32 "
        "{%0,%1,%2,%3},{%4,%5,%6,%7},{%8,%9},{%0,%1,%2,%3};"
        : "+f"(c[0]), "+f"(c[1]), "+f"(c[2]), "+f"(c[3])
        : "r"(a[0]), "r"(a[1]), "r"(a[2]), "r"(a[3]), "r"(bb[0]), "r"(bb[1]));
}

__device__ __forceinline__ void cpa16(char* smem, const char* g) {
    uint32_t s = (uint32_t)__cvta_generic_to_shared(smem);
    asm volatile("cp.async.cg.shared.global [%0], [%1], 16;\n" :: "r"(s), "l"(g) : "memory");
}

static constexpr int STAGE_BYTES = 32768;                // A 16KB + B 16KB
static constexpr int N_STAGES = 3;
static constexpr int GEMM_SMEM = N_STAGES * STAGE_BYTES; // 96 KB

__global__ __launch_bounds__(128, 2) void gemm_kernel(float* __restrict__ Out)
{
    extern __shared__ char sm[];

    int tid = threadIdx.x;
    int warp = tid >> 5, lane = tid & 31;
    int wm = warp >> 1, wn = warp & 1;          // 2x2 warps of 64x64
    int nt = blockIdx.x, mt = blockIdx.y, b = blockIdx.z;

    const char* Ag = (const char*)(g_Afrag + (size_t)mt * 131072);
    const char* Bg = (const char*)(g_Bfrag + ((size_t)b * 32 + nt) * 131072);

#define LOAD(s, kt) do {                                                   \
    char* dst = sm + (s) * STAGE_BYTES;                                    \
    const char* ga = Ag + (size_t)(kt) * 16384;                            \
    const char* gb = Bg + (size_t)(kt) * 16384;                            \
    _Pragma("unroll")                                                      \
    for (int i = 0; i < 8; ++i) {                                          \
        cpa16(dst + i * 2048 + tid * 16,         ga + i * 2048 + tid * 16); \
        cpa16(dst + 16384 + i * 2048 + tid * 16, gb + i * 2048 + tid * 16); \
    }                                                                      \
    asm volatile("cp.async.commit_group;\n" ::: "memory");                 \
} while (0)

    float acc[4][8][4];
    #pragma unroll
    for (int im = 0; im < 4; ++im)
        #pragma unroll
        for (int in = 0; in < 8; ++in)
            #pragma unroll
            for (int r = 0; r < 4; ++r) acc[im][in][r] = 0.f;

    LOAD(0, 0);
    LOAD(1, 1);

    for (int kt = 0; kt < 16; ++kt) {
        int s = kt % 3;
        asm volatile("cp.async.wait_group 1;\n" ::: "memory");
        __syncthreads();
        if (kt + 2 < 16)
            LOAD((kt + 2) % 3, kt + 2);
        else
            asm volatile("cp.async.commit_group;\n" ::: "memory");

        const char* stg = sm + s * STAGE_BYTES;

        #pragma unroll
        for (int kk = 0; kk < 4; ++kk) {
            uint32_t afr[4][4];
            uint32_t bfr[8][2];
            #pragma unroll
            for (int im = 0; im < 4; ++im) {
                uint4 v = *(const uint4*)(stg + kk * 4096 + (wm * 4 + im) * 512 + lane * 16);
                afr[im][0] = v.x; afr[im][1] = v.y;
                afr[im][2] = v.z; afr[im][3] = v.w;
            }
            #pragma unroll
            for (int in = 0; in < 8; ++in) {
                uint2 v = *(const uint2*)(stg + 16384 + kk * 4096 + (wn * 8 + in) * 256 + lane * 8);
                bfr[in][0] = v.x; bfr[in][1] = v.y;
            }
            #pragma unroll
            for (int im = 0; im < 4; ++im)
                #pragma unroll
                for (int in = 0; in < 8; ++in)
                    mma_f16(acc[im][in], afr[im], bfr[in]);
        }
    }

    // epilogue
    float* Og = Out + (size_t)b * 2048 * 4096;
    int g = lane >> 2, tg = lane & 3;
    #pragma unroll
    for (int im = 0; im < 4; ++im) {
        #pragma unroll
        for (int in = 0; in < 8; ++in) {
            int row = mt * 128 + wm * 64 + im * 16 + g;
            int col = nt * 128 + wn * 64 + in * 8 + tg * 2;
            float2 v0 = make_float2(acc[im][in][0], acc[im][in][1]);
            float2 v1 = make_float2(acc[im][in][2], acc[im][in][3]);
            *(float2*)&Og[(size_t)row * 4096 + col]       = v0;
            *(float2*)&Og[(size_t)(row + 8) * 4096 + col] = v1;
        }
    }
#undef LOAD
}

// =====================================================================
extern "C" void kernel_launch(void* const* d_in, const int* in_sizes, int n_in,
                              void* d_out, int out_size)
{
    const float* refer = (const float*)d_in[0];
    const float* sup   = (const float*)d_in[1];
    const float* w_off = (const float*)d_in[2];
    const float* b_off = (const float*)d_in[3];
    const float* w_def = (const float*)d_in[4];
    float* out = (float*)d_out;

    conv_wdef_kernel     <<<dim3(8, 4, 24),  256>>>(refer, sup, w_off, w_def);
    offset_combine_kernel<<<dim3(64, 4),     256>>>(b_off);
    sample_kernel        <<<dim3(16, 4, 16), 256>>>(sup);

    cudaFuncSetAttribute(gemm_kernel, cudaFuncAttributeMaxDynamicSharedMemorySize,
                         GEMM_SMEM);
    gemm_kernel<<<dim3(32, 16, 4), 128, GEMM_SMEM>>>(out);
}

// round 17
// speedup vs baseline: 1.2010x; 1.2010x over previous
#include <cuda_runtime.h>
#include <cuda_fp16.h>
#include <cstdint>

// ---------------- scratch (no mallocs allowed) ----------------
__device__ float g_S[16 * 4 * 18 * 4096];       // conv tap partials, 18.9 MB
__device__ float g_offset[4 * 2 * 4096];        // [b][oc][pix]
// B fp16 mma-fragment order: [b][nt:32][kg:64][n8:16][lane:32][4]  (33.5 MB)
__device__ __half g_Bfrag[4ULL * 32 * 64 * 2048];
// A fp16 mma-fragment order: [mt:16][kg:64][m16:8][lane:32][8]     (4 MB)
__device__ __half g_Afrag[16ULL * 64 * 2048];

#define FMA2(d, a, b, c) \
    asm("fma.rn.f32x2 %0, %1, %2, %3;" : "=l"(d) : "l"(a), "l"(b), "l"(c))

// =====================================================================
// Kernel 1: fused (a) offset-conv tap reduction [z 0..15, 128 ch/split,
// 4 pixel-pairs/thread -> 4 FMA2 per weight-LDS] and (b) w_def -> fp16
// A-fragment repack [z 16..47, 1 unit/block].
// =====================================================================
__global__ __launch_bounds__(256, 2) void conv_wdef_kernel(
    const float* __restrict__ refer, const float* __restrict__ sup,
    const float* __restrict__ w_off, const float* __restrict__ wd)
{
    if (blockIdx.z >= 16) {
        // ---- w_def repack: 512 blocks, 1 unit (256 items) each ----
        int bid = (blockIdx.z - 16) * 16 + blockIdx.y * 4 + blockIdx.x;  // 0..511
        int t = bid * 256 + threadIdx.x;              // (o, kg)
        int o = t >> 6, kg = t & 63;
        int mt = o >> 7, mrow = o & 127;
        int m16 = mrow >> 4, r16 = mrow & 15;
        int g = r16 & 7, hi = r16 >> 3;

        const float* src = wd + (size_t)o * 1024 + kg * 16;
        __half2* dst2 =
            (__half2*)(g_Afrag + (((size_t)mt * 64 + kg) * 8 + m16) * 256);

        #pragma unroll
        for (int p = 0; p < 8; ++p) {
            int c = p * 2;
            int tg = (c & 7) >> 1, chi = c >> 3;
            int lane = g * 4 + tg, reg = hi + 2 * chi;
            dst2[lane * 4 + reg] = __floats2half2_rn(src[c], src[c + 1]);
        }
        return;
    }

    // ---- conv tap reduction: 128 channels per split, taps split 9/9 ----
    __shared__ float2 wsh[128 * 18];                  // 18 KB

    int split = blockIdx.z;
    int b     = blockIdx.y;
    int c0    = split * 128;
    int tid   = threadIdx.x;
    int half  = tid >> 7;               // 0: taps 0-8 (oc0), 1: taps 9-17 (oc1)
    int lt    = tid & 127;

    for (int i = tid; i < 128 * 18; i += 256) {
        int c = i / 18, tap = i - c * 18;
        int oc = tap / 9, t9 = tap - oc * 9;
        float w = w_off[((size_t)oc * 2048 + c0 + c) * 9 + t9];
        wsh[i] = make_float2(w, w);
    }
    __syncthreads();

    const float* src = (c0 < 1024)
        ? refer + ((size_t)b * 1024 + c0) * 4096
        : sup   + ((size_t)b * 1024 + (c0 - 1024)) * 4096;

    // block covers 1024 pixels: pair p at px = bx*1024 + p*256 + lt*2
    int pxb = blockIdx.x * 1024 + lt * 2;
    int toff = half * 9;

    unsigned long long acc[9][4];
    #pragma unroll
    for (int t = 0; t < 9; ++t)
        #pragma unroll
        for (int p = 0; p < 4; ++p) acc[t][p] = 0ull;

    for (int c = 0; c < 128; ++c) {
        const float* chan = src + (size_t)c * 4096 + pxb;
        unsigned long long v[4];
        #pragma unroll
        for (int p = 0; p < 4; ++p)
            v[p] = *(const unsigned long long*)(chan + p * 256);

        const unsigned long long* wp =
            (const unsigned long long*)&wsh[c * 18 + toff];
        #pragma unroll
        for (int t = 0; t < 9; ++t) {
            unsigned long long wv = wp[t];
            #pragma unroll
            for (int p = 0; p < 4; ++p) FMA2(acc[t][p], wv, v[p], acc[t][p]);
        }
    }

    float* outb = g_S + (((size_t)split * 4 + b) * 18) * 4096 + pxb;
    #pragma unroll
    for (int t = 0; t < 9; ++t) {
        float* orow = outb + (size_t)(toff + t) * 4096;
        #pragma unroll
        for (int p = 0; p < 4; ++p)
            *(unsigned long long*)(orow + p * 256) = acc[t][p];
    }
}

// =====================================================================
// Kernel 2: combine shifted taps + reduce 16 splits -> offsets.
// 4 threads per pixel (each 4 splits), batched loads, shfl reduce.
// Grid (64,4).
// =====================================================================
__global__ void offset_combine_kernel(const float* __restrict__ b_off)
{
    int b  = blockIdx.y;
    int pl = threadIdx.x >> 2;          // 0..63 pixel within block
    int q  = threadIdx.x & 3;           // splits q*4 .. q*4+3
    int pix = blockIdx.x * 64 + pl;
    int y = pix >> 6, x = pix & 63;

    float a0[4] = {0.f, 0.f, 0.f, 0.f};
    float a1[4] = {0.f, 0.f, 0.f, 0.f};
    int s0 = q * 4;

    #pragma unroll
    for (int ky = 0; ky < 3; ++ky) {
        int yy = y + ky - 1;
        bool vy = (yy >= 0) && (yy < 64);
        #pragma unroll
        for (int kx = 0; kx < 3; ++kx) {
            int xx = x + kx - 1;
            if (vy && xx >= 0 && xx < 64) {
                int sp = yy * 64 + xx;
                int t9 = ky * 3 + kx;
                float l0[4], l1[4];
                #pragma unroll
                for (int ds = 0; ds < 4; ++ds) {
                    const float* Sb =
                        g_S + (((size_t)(s0 + ds) * 4 + b) * 18) * 4096 + sp;
                    l0[ds] = Sb[(size_t)t9 * 4096];
                    l1[ds] = Sb[(size_t)(9 + t9) * 4096];
                }
                #pragma unroll
                for (int ds = 0; ds < 4; ++ds) {
                    a0[ds] += l0[ds];
                    a1[ds] += l1[ds];
                }
            }
        }
    }

    float r0 = (a0[0] + a0[1]) + (a0[2] + a0[3]);
    float r1 = (a1[0] + a1[1]) + (a1[2] + a1[3]);

    r0 += __shfl_xor_sync(0xFFFFFFFF, r0, 1);
    r0 += __shfl_xor_sync(0xFFFFFFFF, r0, 2);
    r1 += __shfl_xor_sync(0xFFFFFFFF, r1, 1);
    r1 += __shfl_xor_sync(0xFFFFFFFF, r1, 2);

    if (q == 0) {
        g_offset[(b * 2 + 0) * 4096 + pix] = r0 + b_off[0];
        g_offset[(b * 2 + 1) * 4096 + pix] = r1 + b_off[1];
    }
}

// =====================================================================
// Kernel 3: bilinear gather-sample -> B in fp16 mma-fragment order.
// Grid (16 pix strips, 4 batch, 16 channel-64 groups) = 1024 CTAs.
// =====================================================================
__global__ __launch_bounds__(256) void sample_kernel(
    const float* __restrict__ sup)
{
    int pix = blockIdx.x * 256 + threadIdx.x;
    int b   = blockIdx.y;
    int cq  = blockIdx.z;          // 0..15, 64 channels each

    float o0 = g_offset[(b * 2 + 0) * 4096 + pix];
    float o1 = g_offset[(b * 2 + 1) * 4096 + pix];

    int h = pix >> 6, w = pix & 63;
    float py = o0 + (float)h;
    float px = o1 + (float)w;
    float y0f = floorf(py), x0f = floorf(px);
    float wy = py - y0f, wx = px - x0f;
    int y0 = (int)y0f, x0 = (int)x0f;
    int y1 = y0 + 1,  x1 = x0 + 1;

    float vy0 = (y0 >= 0 && y0 < 64) ? 1.f : 0.f;
    float vy1 = (y1 >= 0 && y1 < 64) ? 1.f : 0.f;
    float vx0 = (x0 >= 0 && x0 < 64) ? 1.f : 0.f;
    float vx1 = (x1 >= 0 && x1 < 64) ? 1.f : 0.f;
    int cy0 = min(max(y0, 0), 63), cy1 = min(max(y1, 0), 63);
    int cx0 = min(max(x0, 0), 63), cx1 = min(max(x1, 0), 63);
    int i00 = cy0 * 64 + cx0, i01 = cy0 * 64 + cx1;
    int i10 = cy1 * 64 + cx0, i11 = cy1 * 64 + cx1;
    float w00 = (1.f - wy) * (1.f - wx) * vy0 * vx0;
    float w01 = (1.f - wy) * wx         * vy0 * vx1;
    float w10 = wy * (1.f - wx)         * vy1 * vx0;
    float w11 = wy * wx                 * vy1 * vx1;

    const float* base = sup + ((size_t)b * 1024 + cq * 64) * 4096;

    int nt = pix >> 7, n8 = (pix >> 3) & 15, g = pix & 7;
    __half* outb = g_Bfrag + (((size_t)b * 32 + nt) * 64) * 2048;

    union { uint4 u[2]; __half hbuf[16]; } pack;

    #pragma unroll
    for (int kg16 = 0; kg16 < 4; ++kg16) {
        int kg = cq * 4 + kg16;
        #pragma unroll
        for (int c = 0; c < 16; ++c) {
            const float* p = base + (size_t)(kg16 * 16 + c) * 4096;
            float r = w00 * p[i00] + w01 * p[i01] + w10 * p[i10] + w11 * p[i11];
            int idx = ((c & 7) >> 1) * 4 + (c >> 3) * 2 + (c & 1);
            pack.hbuf[idx] = __float2half_rn(r);
        }
        __half* dst = outb + ((size_t)kg * 16 + n8) * 128 + g * 16;
        *(uint4*)dst       = pack.u[0];
        *(uint4*)(dst + 8) = pack.u[1];
    }
}

// =====================================================================
// Kernel 4: fp16 mma.sync GEMM (m16n8k16, f32 accum).  [frozen]
// 128-thread CTAs: 4 warps (2x2) of 64x64 warp tiles -> CTA 128x128.
// k-tile 64, 3-stage cp.async (96 KB), 2 CTAs/SM.
// =====================================================================
__device__ __forceinline__ void mma_f16(float* c, const uint32_t* a, const uint32_t* bb) {
    asm volatile(
        "mma.sync.aligned.m16n8k16.row.col.f32.f16.f16.f32 "
        "{%0,%1,%2,%3},{%4,%5,%6,%7},{%8,%9},{%0,%1,%2,%3};"
        : "+f"(c[0]), "+f"(c[1]), "+f"(c[2]), "+f"(c[3])
        : "r"(a[0]), "r"(a[1]), "r"(a[2]), "r"(a[3]), "r"(bb[0]), "r"(bb[1]));
}

__device__ __forceinline__ void cpa16(char* smem, const char* g) {
    uint32_t s = (uint32_t)__cvta_generic_to_shared(smem);
    asm volatile("cp.async.cg.shared.global [%0], [%1], 16;\n" :: "r"(s), "l"(g) : "memory");
}

static constexpr int STAGE_BYTES = 32768;                // A 16KB + B 16KB
static constexpr int N_STAGES = 3;
static constexpr int GEMM_SMEM = N_STAGES * STAGE_BYTES; // 96 KB

__global__ __launch_bounds__(128, 2) void gemm_kernel(float* __restrict__ Out)
{
    extern __shared__ char sm[];

    int tid = threadIdx.x;
    int warp = tid >> 5, lane = tid & 31;
    int wm = warp >> 1, wn = warp & 1;          // 2x2 warps of 64x64
    int nt = blockIdx.x, mt = blockIdx.y, b = blockIdx.z;

    const char* Ag = (const char*)(g_Afrag + (size_t)mt * 131072);
    const char* Bg = (const char*)(g_Bfrag + ((size_t)b * 32 + nt) * 131072);

#define LOAD(s, kt) do {                                                   \
    char* dst = sm + (s) * STAGE_BYTES;                                    \
    const char* ga = Ag + (size_t)(kt) * 16384;                            \
    const char* gb = Bg + (size_t)(kt) * 16384;                            \
    _Pragma("unroll")                                                      \
    for (int i = 0; i < 8; ++i) {                                          \
        cpa16(dst + i * 2048 + tid * 16,         ga + i * 2048 + tid * 16); \
        cpa16(dst + 16384 + i * 2048 + tid * 16, gb + i * 2048 + tid * 16); \
    }                                                                      \
    asm volatile("cp.async.commit_group;\n" ::: "memory");                 \
} while (0)

    float acc[4][8][4];
    #pragma unroll
    for (int im = 0; im < 4; ++im)
        #pragma unroll
        for (int in = 0; in < 8; ++in)
            #pragma unroll
            for (int r = 0; r < 4; ++r) acc[im][in][r] = 0.f;

    LOAD(0, 0);
    LOAD(1, 1);

    for (int kt = 0; kt < 16; ++kt) {
        int s = kt % 3;
        asm volatile("cp.async.wait_group 1;\n" ::: "memory");
        __syncthreads();
        if (kt + 2 < 16)
            LOAD((kt + 2) % 3, kt + 2);
        else
            asm volatile("cp.async.commit_group;\n" ::: "memory");

        const char* stg = sm + s * STAGE_BYTES;

        #pragma unroll
        for (int kk = 0; kk < 4; ++kk) {
            uint32_t afr[4][4];
            uint32_t bfr[8][2];
            #pragma unroll
            for (int im = 0; im < 4; ++im) {
                uint4 v = *(const uint4*)(stg + kk * 4096 + (wm * 4 + im) * 512 + lane * 16);
                afr[im][0] = v.x; afr[im][1] = v.y;
                afr[im][2] = v.z; afr[im][3] = v.w;
            }
            #pragma unroll
            for (int in = 0; in < 8; ++in) {
                uint2 v = *(const uint2*)(stg + 16384 + kk * 4096 + (wn * 8 + in) * 256 + lane * 8);
                bfr[in][0] = v.x; bfr[in][1] = v.y;
            }
            #pragma unroll
            for (int im = 0; im < 4; ++im)
                #pragma unroll
                for (int in = 0; in < 8; ++in)
                    mma_f16(acc[im][in], afr[im], bfr[in]);
        }
    }

    // epilogue
    float* Og = Out + (size_t)b * 2048 * 4096;
    int g = lane >> 2, tg = lane & 3;
    #pragma unroll
    for (int im = 0; im < 4; ++im) {
        #pragma unroll
        for (int in = 0; in < 8; ++in) {
            int row = mt * 128 + wm * 64 + im * 16 + g;
            int col = nt * 128 + wn * 64 + in * 8 + tg * 2;
            float2 v0 = make_float2(acc[im][in][0], acc[im][in][1]);
            float2 v1 = make_float2(acc[im][in][2], acc[im][in][3]);
            *(float2*)&Og[(size_t)row * 4096 + col]       = v0;
            *(float2*)&Og[(size_t)(row + 8) * 4096 + col] = v1;
        }
    }
#undef LOAD
}

// =====================================================================
extern "C" void kernel_launch(void* const* d_in, const int* in_sizes, int n_in,
                              void* d_out, int out_size)
{
    const float* refer = (const float*)d_in[0];
    const float* sup   = (const float*)d_in[1];
    const float* w_off = (const float*)d_in[2];
    const float* b_off = (const float*)d_in[3];
    const float* w_def = (const float*)d_in[4];
    float* out = (float*)d_out;

    conv_wdef_kernel     <<<dim3(4, 4, 48),  256>>>(refer, sup, w_off, w_def);
    offset_combine_kernel<<<dim3(64, 4),     256>>>(b_off);
    sample_kernel        <<<dim3(16, 4, 16), 256>>>(sup);

    cudaFuncSetAttribute(gemm_kernel, cudaFuncAttributeMaxDynamicSharedMemorySize,
                         GEMM_SMEM);
    gemm_kernel<<<dim3(32, 16, 4), 128, GEMM_SMEM>>>(out);
}